// round 1
// baseline (speedup 1.0000x reference)
#include <cuda_runtime.h>

#define NN   524288      // nodes
#define NE   12582912    // edges
#define NB   64          // graphs
#define NPER 8192        // nodes per graph
#define F0   8
#define HID  5

// ---------------- device scratch (static; no allocation allowed) ----------------
struct __align__(32) Rec { float ea0, ea1, ea2, ea3; int src; int pad0, pad1, pad2; };

__device__ float  g_xn[NN * F0];       // normalized x
__device__ float  g_h1[NN * HID];      // layer-1 output
__device__ float  g_h2[NN * HID];      // layer-2 output
__device__ float  g_xl[NN * HID];
__device__ float  g_xr[NN * HID];
__device__ int    g_cnt[NN];
__device__ int    g_tmp[NN];
__device__ int    g_rowptr[NN + 1];
__device__ int    g_fill[NN];
__device__ int    g_btot[512];
__device__ int    g_btots[512];
__device__ Rec    g_rec[NE];           // 402 MB CSR records
__device__ double g_easum[4];
__device__ float4 g_eamean;
__device__ float  g_pool[NB * 18];

// ---------------- zero per-launch state ----------------
__global__ void k_zero() {
    int i = blockIdx.x * blockDim.x + threadIdx.x;
    if (i < NN) g_cnt[i] = 0;
    if (i < 4)  g_easum[i] = 0.0;
}

// ---------------- GraphNorm (one block per graph; contiguous batch) ----------------
__global__ void k_gn(const float* __restrict__ x, const float* __restrict__ w,
                     const float* __restrict__ b, const float* __restrict__ ms) {
    int g = blockIdx.x, tid = threadIdx.x;
    float s1[F0], s2[F0];
#pragma unroll
    for (int f = 0; f < F0; f++) { s1[f] = 0.f; s2[f] = 0.f; }
    for (int r = tid; r < NPER; r += blockDim.x) {
        const float* row = x + (size_t)(g * NPER + r) * F0;
#pragma unroll
        for (int f = 0; f < F0; f++) { float v = row[f]; s1[f] += v; s2[f] += v * v; }
    }
#pragma unroll
    for (int off = 16; off > 0; off >>= 1)
#pragma unroll
        for (int f = 0; f < F0; f++) {
            s1[f] += __shfl_xor_sync(0xffffffffu, s1[f], off);
            s2[f] += __shfl_xor_sync(0xffffffffu, s2[f], off);
        }
    __shared__ float sm[8][2 * F0];
    int wp = tid >> 5, lane = tid & 31;
    if (lane == 0) {
#pragma unroll
        for (int f = 0; f < F0; f++) { sm[wp][f] = s1[f]; sm[wp][F0 + f] = s2[f]; }
    }
    __syncthreads();
    __shared__ float meanms[F0], scale[F0], bias[F0];
    if (tid < F0) {
        float t1 = 0.f, t2 = 0.f;
        for (int k = 0; k < 8; k++) { t1 += sm[k][tid]; t2 += sm[k][F0 + tid]; }
        float mean = t1 / (float)NPER, ex2 = t2 / (float)NPER, m = ms[tid];
        float var = ex2 - 2.f * m * mean * mean + m * m * mean * mean;
        meanms[tid] = m * mean;
        scale[tid] = w[tid] * rsqrtf(var + 1e-5f);
        bias[tid] = b[tid];
    }
    __syncthreads();
    for (int r = tid; r < NPER; r += blockDim.x) {
        const float* row = x + (size_t)(g * NPER + r) * F0;
        float* orow = g_xn + (size_t)(g * NPER + r) * F0;
#pragma unroll
        for (int f = 0; f < F0; f++) orow[f] = scale[f] * (row[f] - meanms[f]) + bias[f];
    }
}

// ---------------- CSR build ----------------
__global__ void k_count(const int* __restrict__ dst) {
    int stride = gridDim.x * blockDim.x;
    for (int e = blockIdx.x * blockDim.x + threadIdx.x; e < NE; e += stride)
        atomicAdd(&g_cnt[dst[e]], 1);
}

__global__ void k_scanA() {   // 512 blocks x 1024 threads
    __shared__ int s[1024];
    int tid = threadIdx.x;
    int idx = blockIdx.x * 1024 + tid;
    int v = g_cnt[idx];
    s[tid] = v;
    __syncthreads();
    for (int off = 1; off < 1024; off <<= 1) {
        int t = (tid >= off) ? s[tid - off] : 0;
        __syncthreads();
        s[tid] += t;
        __syncthreads();
    }
    g_tmp[idx] = s[tid] - v;                 // exclusive within block
    if (tid == 1023) g_btot[blockIdx.x] = s[1023];
}

__global__ void k_scanB() {   // 1 block x 512 threads
    __shared__ int s[512];
    int tid = threadIdx.x;
    int v = g_btot[tid];
    s[tid] = v;
    __syncthreads();
    for (int off = 1; off < 512; off <<= 1) {
        int t = (tid >= off) ? s[tid - off] : 0;
        __syncthreads();
        s[tid] += t;
        __syncthreads();
    }
    g_btots[tid] = s[tid] - v;
}

__global__ void k_scanC() {   // 512 blocks x 1024 threads
    int idx = blockIdx.x * 1024 + threadIdx.x;
    int p = g_tmp[idx] + g_btots[blockIdx.x];
    g_rowptr[idx] = p;
    g_fill[idx] = p;
    if (idx == 0) g_rowptr[NN] = NE;
}

__global__ void k_scatter(const int* __restrict__ src, const int* __restrict__ dst,
                          const float* __restrict__ ea) {
    int stride = gridDim.x * blockDim.x;
    double a0 = 0.0, a1 = 0.0, a2 = 0.0, a3 = 0.0;
    for (int e = blockIdx.x * blockDim.x + threadIdx.x; e < NE; e += stride) {
        float4 v = __ldg((const float4*)(ea + (size_t)e * 4));
        int s = src[e], dnode = dst[e];
        a0 += v.x; a1 += v.y; a2 += v.z; a3 += v.w;
        int p = atomicAdd(&g_fill[dnode], 1);
        Rec* r = &g_rec[p];
        *(float4*)&r->ea0 = v;
        *(int4*)&r->src = make_int4(s, 0, 0, 0);
    }
    // block-reduce edge_attr sums (double) for self-loop mean
#pragma unroll
    for (int off = 16; off > 0; off >>= 1) {
        a0 += __shfl_xor_sync(0xffffffffu, a0, off);
        a1 += __shfl_xor_sync(0xffffffffu, a1, off);
        a2 += __shfl_xor_sync(0xffffffffu, a2, off);
        a3 += __shfl_xor_sync(0xffffffffu, a3, off);
    }
    __shared__ double sd[8][4];
    int wp = threadIdx.x >> 5, lane = threadIdx.x & 31;
    if (lane == 0) { sd[wp][0] = a0; sd[wp][1] = a1; sd[wp][2] = a2; sd[wp][3] = a3; }
    __syncthreads();
    if (threadIdx.x < 4) {
        double t = 0.0;
        for (int k = 0; k < 8; k++) t += sd[k][threadIdx.x];
        atomicAdd(&g_easum[threadIdx.x], t);
    }
}

__global__ void k_eamean() {
    if (threadIdx.x == 0) {
        double inv = 1.0 / (double)NE;
        g_eamean = make_float4((float)(g_easum[0] * inv), (float)(g_easum[1] * inv),
                               (float)(g_easum[2] * inv), (float)(g_easum[3] * inv));
    }
}

// ---------------- per-node linear transforms xl / xr ----------------
template<bool SECOND>
__global__ void k_lr(const float* __restrict__ Wl, const float* __restrict__ bl,
                     const float* __restrict__ Wr, const float* __restrict__ br) {
    int n = blockIdx.x * blockDim.x + threadIdx.x;
    if (n >= NN) return;
    const int FIN = SECOND ? 13 : 8;
    float xv[13];
    if (SECOND) {
#pragma unroll
        for (int j = 0; j < 5; j++) xv[j] = g_h1[n * 5 + j];
#pragma unroll
        for (int f = 0; f < 8; f++) xv[5 + f] = g_xn[n * 8 + f];
    } else {
#pragma unroll
        for (int f = 0; f < 8; f++) xv[f] = g_xn[n * 8 + f];
    }
    float l[5], r[5];
#pragma unroll
    for (int j = 0; j < 5; j++) { l[j] = bl[j]; r[j] = br[j]; }
#pragma unroll
    for (int i = 0; i < FIN; i++)
#pragma unroll
        for (int j = 0; j < 5; j++) {
            l[j] = fmaf(xv[i], Wl[i * 5 + j], l[j]);
            r[j] = fmaf(xv[i], Wr[i * 5 + j], r[j]);
        }
#pragma unroll
    for (int j = 0; j < 5; j++) { g_xl[n * 5 + j] = l[j]; g_xr[n * 5 + j] = r[j]; }
}

// ---------------- GATv2 layer: one warp per node, online softmax ----------------
template<int L>
__global__ void k_gat(const float* __restrict__ We, const float* __restrict__ att,
                      const float* __restrict__ bo) {
    const int lane = threadIdx.x & 31;
    const int node = blockIdx.x * (256 / 32) + (threadIdx.x >> 5);
    float* __restrict__ hout = (L == 1) ? g_h1 : g_h2;

    float we[4][5], av[5];
#pragma unroll
    for (int k = 0; k < 4; k++)
#pragma unroll
        for (int j = 0; j < 5; j++) we[k][j] = We[k * 5 + j];
#pragma unroll
    for (int j = 0; j < 5; j++) av[j] = att[j];

    float xrv[5], xlv[5];
#pragma unroll
    for (int j = 0; j < 5; j++) { xrv[j] = g_xr[node * 5 + j]; xlv[j] = g_xl[node * 5 + j]; }

    int beg = g_rowptr[node], end = g_rowptr[node + 1];

    float m = -1e30f, d = 0.f;
    float num[5] = {0.f, 0.f, 0.f, 0.f, 0.f};

    for (int i = beg + lane; i < end; i += 32) {
        const Rec* r = &g_rec[i];
        float4 eav = *(const float4*)&r->ea0;
        int s = r->src;
        float v[5], logit = 0.f;
#pragma unroll
        for (int j = 0; j < 5; j++) {
            v[j] = g_xl[s * 5 + j];
            float e = v[j] + xrv[j];
            e = fmaf(eav.x, we[0][j], e);
            e = fmaf(eav.y, we[1][j], e);
            e = fmaf(eav.z, we[2][j], e);
            e = fmaf(eav.w, we[3][j], e);
            e = (e > 0.f) ? e : 0.2f * e;
            logit = fmaf(av[j], e, logit);
        }
        if (logit > m) {
            float c = __expf(m - logit);
            d = fmaf(d, c, 1.f);
#pragma unroll
            for (int j = 0; j < 5; j++) num[j] = fmaf(num[j], c, v[j]);
            m = logit;
        } else {
            float c = __expf(logit - m);
            d += c;
#pragma unroll
            for (int j = 0; j < 5; j++) num[j] = fmaf(c, v[j], num[j]);
        }
    }

    // self-loop contribution (edge_attr = global mean), lane 0
    if (lane == 0) {
        float4 eav = g_eamean;
        float logit = 0.f;
#pragma unroll
        for (int j = 0; j < 5; j++) {
            float e = xlv[j] + xrv[j];
            e = fmaf(eav.x, we[0][j], e);
            e = fmaf(eav.y, we[1][j], e);
            e = fmaf(eav.z, we[2][j], e);
            e = fmaf(eav.w, we[3][j], e);
            e = (e > 0.f) ? e : 0.2f * e;
            logit = fmaf(av[j], e, logit);
        }
        if (logit > m) {
            float c = __expf(m - logit);
            d = fmaf(d, c, 1.f);
#pragma unroll
            for (int j = 0; j < 5; j++) num[j] = fmaf(num[j], c, xlv[j]);
            m = logit;
        } else {
            float c = __expf(logit - m);
            d += c;
#pragma unroll
            for (int j = 0; j < 5; j++) num[j] = fmaf(c, xlv[j], num[j]);
        }
    }

    // warp butterfly combine of online-softmax states
#pragma unroll
    for (int off = 16; off > 0; off >>= 1) {
        float m2 = __shfl_xor_sync(0xffffffffu, m, off);
        float d2 = __shfl_xor_sync(0xffffffffu, d, off);
        float n2[5];
#pragma unroll
        for (int j = 0; j < 5; j++) n2[j] = __shfl_xor_sync(0xffffffffu, num[j], off);
        float M = fmaxf(m, m2);
        float c1 = __expf(m - M), c2 = __expf(m2 - M);
        d = d * c1 + d2 * c2;
#pragma unroll
        for (int j = 0; j < 5; j++) num[j] = num[j] * c1 + n2[j] * c2;
        m = M;
    }

    if (lane == 0) {
        float inv = 1.f / d;
#pragma unroll
        for (int j = 0; j < 5; j++) {
            float h = fmaf(num[j], inv, bo[j]);
            hout[node * 5 + j] = (h > 0.f) ? h : 0.f;
        }
    }
}

// ---------------- mean pool per graph (on virtual concat [h2,h1,xn]) ----------------
__global__ void k_pool() {
    int g = blockIdx.x, tid = threadIdx.x;
    float acc[18];
#pragma unroll
    for (int f = 0; f < 18; f++) acc[f] = 0.f;
    for (int r = tid; r < NPER; r += blockDim.x) {
        int n = g * NPER + r;
#pragma unroll
        for (int j = 0; j < 5; j++) acc[j] += g_h2[n * 5 + j];
#pragma unroll
        for (int j = 0; j < 5; j++) acc[5 + j] += g_h1[n * 5 + j];
#pragma unroll
        for (int f = 0; f < 8; f++) acc[10 + f] += g_xn[n * 8 + f];
    }
#pragma unroll
    for (int off = 16; off > 0; off >>= 1)
#pragma unroll
        for (int f = 0; f < 18; f++) acc[f] += __shfl_xor_sync(0xffffffffu, acc[f], off);
    __shared__ float sm[8][18];
    int wp = tid >> 5, lane = tid & 31;
    if (lane == 0) {
#pragma unroll
        for (int f = 0; f < 18; f++) sm[wp][f] = acc[f];
    }
    __syncthreads();
    if (tid < 18) {
        float t = 0.f;
        for (int k = 0; k < 8; k++) t += sm[k][tid];
        g_pool[g * 18 + tid] = t * (1.f / (float)NPER);
    }
}

// ---------------- dueling head ----------------
__global__ void k_head(const int* __restrict__ cur, const int* __restrict__ mask,
                       const float* __restrict__ goal,
                       const float* __restrict__ Wv1, const float* __restrict__ bv1,
                       const float* __restrict__ Wv2, const float* __restrict__ bv2,
                       const float* __restrict__ Wa1, const float* __restrict__ ba1,
                       const float* __restrict__ Wa2, const float* __restrict__ ba2,
                       float* __restrict__ out) {
    int b = threadIdx.x;
    if (b >= NB) return;
    int n = b * NPER + cur[b];
    float feat[42];
#pragma unroll
    for (int j = 0; j < 5; j++) feat[j] = g_h2[n * 5 + j];
#pragma unroll
    for (int j = 0; j < 5; j++) feat[5 + j] = g_h1[n * 5 + j];
#pragma unroll
    for (int f = 0; f < 8; f++) feat[10 + f] = g_xn[n * 8 + f];
#pragma unroll
    for (int k = 0; k < 18; k++) feat[18 + k] = g_pool[b * 18 + k];
#pragma unroll
    for (int k = 0; k < 6; k++) feat[36 + k] = goal[b * 6 + k];

    float hv[10], ha[10];
#pragma unroll
    for (int j = 0; j < 10; j++) { hv[j] = bv1[j]; ha[j] = ba1[j]; }
    for (int i = 0; i < 42; i++) {
        float fi = feat[i];
#pragma unroll
        for (int j = 0; j < 10; j++) {
            hv[j] = fmaf(fi, Wv1[i * 10 + j], hv[j]);
            ha[j] = fmaf(fi, Wa1[i * 10 + j], ha[j]);
        }
    }
#pragma unroll
    for (int j = 0; j < 10; j++) {
        hv[j] = (hv[j] > 0.f) ? hv[j] : 0.f;
        ha[j] = (ha[j] > 0.f) ? ha[j] : 0.f;
    }
    float val = bv2[0];
#pragma unroll
    for (int j = 0; j < 10; j++) val = fmaf(hv[j], Wv2[j], val);
    float adv[4];
#pragma unroll
    for (int k = 0; k < 4; k++) {
        adv[k] = ba2[k];
#pragma unroll
        for (int j = 0; j < 10; j++) adv[k] = fmaf(ha[j], Wa2[j * 4 + k], adv[k]);
    }
    float am = (adv[0] + adv[1] + adv[2] + adv[3]) * 0.25f;
#pragma unroll
    for (int k = 0; k < 4; k++)
        out[b * 4 + k] = (mask[b * 4 + k] == 0) ? -1e8f : (val + adv[k] - am);
}

// ---------------- launch ----------------
extern "C" void kernel_launch(void* const* d_in, const int* in_sizes, int n_in,
                              void* d_out, int out_size) {
    const float* x    = (const float*)d_in[0];
    const int*   ei   = (const int*)d_in[1];
    const float* ea   = (const float*)d_in[2];
    const int*   cur  = (const int*)d_in[4];
    const int*   mask = (const int*)d_in[5];
    const float* goal = (const float*)d_in[6];
    const float* gnw  = (const float*)d_in[7];
    const float* gnb  = (const float*)d_in[8];
    const float* gnms = (const float*)d_in[9];
    const float* Wl1 = (const float*)d_in[10], *bl1 = (const float*)d_in[11];
    const float* Wr1 = (const float*)d_in[12], *br1 = (const float*)d_in[13];
    const float* We1 = (const float*)d_in[14], *att1 = (const float*)d_in[15], *bo1 = (const float*)d_in[16];
    const float* Wl2 = (const float*)d_in[17], *bl2 = (const float*)d_in[18];
    const float* Wr2 = (const float*)d_in[19], *br2 = (const float*)d_in[20];
    const float* We2 = (const float*)d_in[21], *att2 = (const float*)d_in[22], *bo2 = (const float*)d_in[23];
    const float* Wv1 = (const float*)d_in[24], *bv1 = (const float*)d_in[25];
    const float* Wv2 = (const float*)d_in[26], *bv2 = (const float*)d_in[27];
    const float* Wa1 = (const float*)d_in[28], *ba1 = (const float*)d_in[29];
    const float* Wa2 = (const float*)d_in[30], *ba2 = (const float*)d_in[31];

    const int* srcp = ei;
    const int* dstp = ei + NE;

    k_zero<<<(NN + 255) / 256, 256>>>();
    k_gn<<<NB, 256>>>(x, gnw, gnb, gnms);
    k_count<<<4096, 256>>>(dstp);
    k_scanA<<<512, 1024>>>();
    k_scanB<<<1, 512>>>();
    k_scanC<<<512, 1024>>>();
    k_scatter<<<4096, 256>>>(srcp, dstp, ea);
    k_eamean<<<1, 32>>>();

    k_lr<false><<<(NN + 255) / 256, 256>>>(Wl1, bl1, Wr1, br1);
    k_gat<1><<<NN / 8, 256>>>(We1, att1, bo1);

    k_lr<true><<<(NN + 255) / 256, 256>>>(Wl2, bl2, Wr2, br2);
    k_gat<2><<<NN / 8, 256>>>(We2, att2, bo2);

    k_pool<<<NB, 256>>>();
    k_head<<<1, 64>>>(cur, mask, goal, Wv1, bv1, Wv2, bv2, Wa1, ba1, Wa2, ba2,
                      (float*)d_out);
}

// round 2
// speedup vs baseline: 1.0171x; 1.0171x over previous
#include <cuda_runtime.h>

#define NN   524288      // nodes
#define NE   12582912    // edges
#define NB   64          // graphs
#define NPER 8192        // nodes per graph
#define F0   8
#define HID  5

// ---------------- device scratch (static; no allocation allowed) ----------------
// 16B record: ea(float4) with the 19-bit src index packed into mantissa LSBs
// (5 bits in x, 5 in y, 5 in z, 4 in w). Perturbs ea by <= 2^-18 relative.
__device__ uint4  g_rec[NE];           // 201 MB CSR records
__device__ float  g_xn[NN * F0];       // normalized x
__device__ float  g_h1[NN * HID];      // layer-1 output
__device__ float  g_h2[NN * HID];      // layer-2 output
__device__ float  g_xl[NN * 8];        // padded to 32B rows (one sector per gather)
__device__ float  g_xr[NN * 8];
__device__ int    g_cnt[NN];
__device__ int    g_tmp[NN];
__device__ int    g_rowptr[NN + 1];
__device__ int    g_fill[NN];
__device__ int    g_btot[512];
__device__ int    g_btots[512];
__device__ double g_easum[4];
__device__ float4 g_eamean;
__device__ float  g_pool[NB * 18];

// ---------------- zero per-launch state ----------------
__global__ void k_zero() {
    int i = blockIdx.x * blockDim.x + threadIdx.x;
    if (i < NN) g_cnt[i] = 0;
    if (i < 4)  g_easum[i] = 0.0;
}

// ---------------- GraphNorm (one block per graph; contiguous batch) ----------------
__global__ void k_gn(const float* __restrict__ x, const float* __restrict__ w,
                     const float* __restrict__ b, const float* __restrict__ ms) {
    int g = blockIdx.x, tid = threadIdx.x;
    float s1[F0], s2[F0];
#pragma unroll
    for (int f = 0; f < F0; f++) { s1[f] = 0.f; s2[f] = 0.f; }
    for (int r = tid; r < NPER; r += blockDim.x) {
        const float* row = x + (size_t)(g * NPER + r) * F0;
#pragma unroll
        for (int f = 0; f < F0; f++) { float v = row[f]; s1[f] += v; s2[f] += v * v; }
    }
#pragma unroll
    for (int off = 16; off > 0; off >>= 1)
#pragma unroll
        for (int f = 0; f < F0; f++) {
            s1[f] += __shfl_xor_sync(0xffffffffu, s1[f], off);
            s2[f] += __shfl_xor_sync(0xffffffffu, s2[f], off);
        }
    __shared__ float sm[8][2 * F0];
    int wp = tid >> 5, lane = tid & 31;
    if (lane == 0) {
#pragma unroll
        for (int f = 0; f < F0; f++) { sm[wp][f] = s1[f]; sm[wp][F0 + f] = s2[f]; }
    }
    __syncthreads();
    __shared__ float meanms[F0], scale[F0], bias[F0];
    if (tid < F0) {
        float t1 = 0.f, t2 = 0.f;
        for (int k = 0; k < 8; k++) { t1 += sm[k][tid]; t2 += sm[k][F0 + tid]; }
        float mean = t1 / (float)NPER, ex2 = t2 / (float)NPER, m = ms[tid];
        float var = ex2 - 2.f * m * mean * mean + m * m * mean * mean;
        meanms[tid] = m * mean;
        scale[tid] = w[tid] * rsqrtf(var + 1e-5f);
        bias[tid] = b[tid];
    }
    __syncthreads();
    for (int r = tid; r < NPER; r += blockDim.x) {
        const float* row = x + (size_t)(g * NPER + r) * F0;
        float* orow = g_xn + (size_t)(g * NPER + r) * F0;
#pragma unroll
        for (int f = 0; f < F0; f++) orow[f] = scale[f] * (row[f] - meanms[f]) + bias[f];
    }
}

// ---------------- CSR build ----------------
__global__ void k_count(const int* __restrict__ dst) {
    int stride = gridDim.x * blockDim.x;
    const int4* d4 = (const int4*)dst;
    for (int e = blockIdx.x * blockDim.x + threadIdx.x; e < NE / 4; e += stride) {
        int4 d = __ldg(d4 + e);
        atomicAdd(&g_cnt[d.x], 1);
        atomicAdd(&g_cnt[d.y], 1);
        atomicAdd(&g_cnt[d.z], 1);
        atomicAdd(&g_cnt[d.w], 1);
    }
}

__global__ void k_scanA() {   // 512 blocks x 1024 threads
    __shared__ int s[1024];
    int tid = threadIdx.x;
    int idx = blockIdx.x * 1024 + tid;
    int v = g_cnt[idx];
    s[tid] = v;
    __syncthreads();
    for (int off = 1; off < 1024; off <<= 1) {
        int t = (tid >= off) ? s[tid - off] : 0;
        __syncthreads();
        s[tid] += t;
        __syncthreads();
    }
    g_tmp[idx] = s[tid] - v;                 // exclusive within block
    if (tid == 1023) g_btot[blockIdx.x] = s[1023];
}

__global__ void k_scanB() {   // 1 block x 512 threads
    __shared__ int s[512];
    int tid = threadIdx.x;
    int v = g_btot[tid];
    s[tid] = v;
    __syncthreads();
    for (int off = 1; off < 512; off <<= 1) {
        int t = (tid >= off) ? s[tid - off] : 0;
        __syncthreads();
        s[tid] += t;
        __syncthreads();
    }
    g_btots[tid] = s[tid] - v;
}

__global__ void k_scanC() {   // 512 blocks x 1024 threads
    int idx = blockIdx.x * 1024 + threadIdx.x;
    int p = g_tmp[idx] + g_btots[blockIdx.x];
    g_rowptr[idx] = p;
    g_fill[idx] = p;
    if (idx == 0) g_rowptr[NN] = NE;
}

__device__ __forceinline__ uint4 pack_rec(float4 v, int s) {
    uint4 u;
    u.x = (__float_as_uint(v.x) & ~31u) | ((unsigned)s >> 14);
    u.y = (__float_as_uint(v.y) & ~31u) | (((unsigned)s >> 9) & 31u);
    u.z = (__float_as_uint(v.z) & ~31u) | (((unsigned)s >> 4) & 31u);
    u.w = (__float_as_uint(v.w) & ~15u) | ((unsigned)s & 15u);
    return u;
}

__global__ void k_scatter(const int* __restrict__ src, const int* __restrict__ dst,
                          const float* __restrict__ ea) {
    int stride = gridDim.x * blockDim.x;
    const int4* s4 = (const int4*)src;
    const int4* d4 = (const int4*)dst;
    const float4* e4 = (const float4*)ea;
    double a0 = 0.0, a1 = 0.0, a2 = 0.0, a3 = 0.0;
    for (int e = blockIdx.x * blockDim.x + threadIdx.x; e < NE / 4; e += stride) {
        int4 ss = __ldg(s4 + e);
        int4 dd = __ldg(d4 + e);
        float4 v0 = __ldg(e4 + (size_t)e * 4 + 0);
        float4 v1 = __ldg(e4 + (size_t)e * 4 + 1);
        float4 v2 = __ldg(e4 + (size_t)e * 4 + 2);
        float4 v3 = __ldg(e4 + (size_t)e * 4 + 3);
        a0 += (double)v0.x + v1.x + v2.x + v3.x;
        a1 += (double)v0.y + v1.y + v2.y + v3.y;
        a2 += (double)v0.z + v1.z + v2.z + v3.z;
        a3 += (double)v0.w + v1.w + v2.w + v3.w;
        g_rec[atomicAdd(&g_fill[dd.x], 1)] = pack_rec(v0, ss.x);
        g_rec[atomicAdd(&g_fill[dd.y], 1)] = pack_rec(v1, ss.y);
        g_rec[atomicAdd(&g_fill[dd.z], 1)] = pack_rec(v2, ss.z);
        g_rec[atomicAdd(&g_fill[dd.w], 1)] = pack_rec(v3, ss.w);
    }
#pragma unroll
    for (int off = 16; off > 0; off >>= 1) {
        a0 += __shfl_xor_sync(0xffffffffu, a0, off);
        a1 += __shfl_xor_sync(0xffffffffu, a1, off);
        a2 += __shfl_xor_sync(0xffffffffu, a2, off);
        a3 += __shfl_xor_sync(0xffffffffu, a3, off);
    }
    __shared__ double sd[8][4];
    int wp = threadIdx.x >> 5, lane = threadIdx.x & 31;
    if (lane == 0) { sd[wp][0] = a0; sd[wp][1] = a1; sd[wp][2] = a2; sd[wp][3] = a3; }
    __syncthreads();
    if (threadIdx.x < 4) {
        double t = 0.0;
        for (int k = 0; k < 8; k++) t += sd[k][threadIdx.x];
        atomicAdd(&g_easum[threadIdx.x], t);
    }
}

__global__ void k_eamean() {
    if (threadIdx.x == 0) {
        double inv = 1.0 / (double)NE;
        g_eamean = make_float4((float)(g_easum[0] * inv), (float)(g_easum[1] * inv),
                               (float)(g_easum[2] * inv), (float)(g_easum[3] * inv));
    }
}

// ---------------- per-node linear transforms xl / xr (padded stride-8 output) ----------------
template<bool SECOND>
__global__ void k_lr(const float* __restrict__ Wl, const float* __restrict__ bl,
                     const float* __restrict__ Wr, const float* __restrict__ br) {
    int n = blockIdx.x * blockDim.x + threadIdx.x;
    if (n >= NN) return;
    const int FIN = SECOND ? 13 : 8;
    float xv[13];
    if (SECOND) {
#pragma unroll
        for (int j = 0; j < 5; j++) xv[j] = g_h1[n * 5 + j];
#pragma unroll
        for (int f = 0; f < 8; f++) xv[5 + f] = g_xn[n * 8 + f];
    } else {
#pragma unroll
        for (int f = 0; f < 8; f++) xv[f] = g_xn[n * 8 + f];
    }
    float l[5], r[5];
#pragma unroll
    for (int j = 0; j < 5; j++) { l[j] = bl[j]; r[j] = br[j]; }
#pragma unroll
    for (int i = 0; i < FIN; i++)
#pragma unroll
        for (int j = 0; j < 5; j++) {
            l[j] = fmaf(xv[i], Wl[i * 5 + j], l[j]);
            r[j] = fmaf(xv[i], Wr[i * 5 + j], r[j]);
        }
    float4* lp = (float4*)(g_xl + n * 8);
    float4* rp = (float4*)(g_xr + n * 8);
    lp[0] = make_float4(l[0], l[1], l[2], l[3]);
    lp[1] = make_float4(l[4], 0.f, 0.f, 0.f);
    rp[0] = make_float4(r[0], r[1], r[2], r[3]);
    rp[1] = make_float4(r[4], 0.f, 0.f, 0.f);
}

// ---------------- GATv2 layer: one warp per node, online softmax ----------------
template<int L>
__global__ void k_gat(const float* __restrict__ We, const float* __restrict__ att,
                      const float* __restrict__ bo) {
    const int lane = threadIdx.x & 31;
    const int node = blockIdx.x * (256 / 32) + (threadIdx.x >> 5);
    float* __restrict__ hout = (L == 1) ? g_h1 : g_h2;

    float we[4][5], av[5];
#pragma unroll
    for (int k = 0; k < 4; k++)
#pragma unroll
        for (int j = 0; j < 5; j++) we[k][j] = We[k * 5 + j];
#pragma unroll
    for (int j = 0; j < 5; j++) av[j] = att[j];

    float xrv[5], xlv[5];
    {
        float4 r0 = *(const float4*)(g_xr + node * 8);
        xrv[0] = r0.x; xrv[1] = r0.y; xrv[2] = r0.z; xrv[3] = r0.w;
        xrv[4] = g_xr[node * 8 + 4];
        float4 l0 = *(const float4*)(g_xl + node * 8);
        xlv[0] = l0.x; xlv[1] = l0.y; xlv[2] = l0.z; xlv[3] = l0.w;
        xlv[4] = g_xl[node * 8 + 4];
    }

    int beg = g_rowptr[node], end = g_rowptr[node + 1];

    float m = -1e30f, d = 0.f;
    float num[5] = {0.f, 0.f, 0.f, 0.f, 0.f};

    for (int i = beg + lane; i < end; i += 32) {
        uint4 u = g_rec[i];
        int s = (int)(((u.x & 31u) << 14) | ((u.y & 31u) << 9) |
                      ((u.z & 31u) << 4) | (u.w & 15u));
        float eax = __uint_as_float(u.x), eay = __uint_as_float(u.y);
        float eaz = __uint_as_float(u.z), eaw = __uint_as_float(u.w);
        float v[5];
        float4 v0 = *(const float4*)(g_xl + s * 8);
        v[0] = v0.x; v[1] = v0.y; v[2] = v0.z; v[3] = v0.w;
        v[4] = g_xl[s * 8 + 4];
        float logit = 0.f;
#pragma unroll
        for (int j = 0; j < 5; j++) {
            float e = v[j] + xrv[j];
            e = fmaf(eax, we[0][j], e);
            e = fmaf(eay, we[1][j], e);
            e = fmaf(eaz, we[2][j], e);
            e = fmaf(eaw, we[3][j], e);
            e = (e > 0.f) ? e : 0.2f * e;
            logit = fmaf(av[j], e, logit);
        }
        if (logit > m) {
            float c = __expf(m - logit);
            d = fmaf(d, c, 1.f);
#pragma unroll
            for (int j = 0; j < 5; j++) num[j] = fmaf(num[j], c, v[j]);
            m = logit;
        } else {
            float c = __expf(logit - m);
            d += c;
#pragma unroll
            for (int j = 0; j < 5; j++) num[j] = fmaf(c, v[j], num[j]);
        }
    }

    // self-loop contribution (edge_attr = global mean), lane 0
    if (lane == 0) {
        float4 eav = g_eamean;
        float logit = 0.f;
#pragma unroll
        for (int j = 0; j < 5; j++) {
            float e = xlv[j] + xrv[j];
            e = fmaf(eav.x, we[0][j], e);
            e = fmaf(eav.y, we[1][j], e);
            e = fmaf(eav.z, we[2][j], e);
            e = fmaf(eav.w, we[3][j], e);
            e = (e > 0.f) ? e : 0.2f * e;
            logit = fmaf(av[j], e, logit);
        }
        if (logit > m) {
            float c = __expf(m - logit);
            d = fmaf(d, c, 1.f);
#pragma unroll
            for (int j = 0; j < 5; j++) num[j] = fmaf(num[j], c, xlv[j]);
            m = logit;
        } else {
            float c = __expf(logit - m);
            d += c;
#pragma unroll
            for (int j = 0; j < 5; j++) num[j] = fmaf(c, xlv[j], num[j]);
        }
    }

    // warp combine: max-butterfly, one rescale, then 6-value sum-butterfly
    float M = m;
#pragma unroll
    for (int off = 16; off > 0; off >>= 1)
        M = fmaxf(M, __shfl_xor_sync(0xffffffffu, M, off));
    float c = __expf(m - M);           // lanes with no edges: exp(-inf) = 0
    d *= c;
#pragma unroll
    for (int j = 0; j < 5; j++) num[j] *= c;
#pragma unroll
    for (int off = 16; off > 0; off >>= 1) {
        d += __shfl_xor_sync(0xffffffffu, d, off);
#pragma unroll
        for (int j = 0; j < 5; j++) num[j] += __shfl_xor_sync(0xffffffffu, num[j], off);
    }

    if (lane == 0) {
        float inv = 1.f / d;
#pragma unroll
        for (int j = 0; j < 5; j++) {
            float h = fmaf(num[j], inv, bo[j]);
            hout[node * 5 + j] = (h > 0.f) ? h : 0.f;
        }
    }
}

// ---------------- mean pool per graph (on virtual concat [h2,h1,xn]) ----------------
__global__ void k_pool() {
    int g = blockIdx.x, tid = threadIdx.x;
    float acc[18];
#pragma unroll
    for (int f = 0; f < 18; f++) acc[f] = 0.f;
    for (int r = tid; r < NPER; r += blockDim.x) {
        int n = g * NPER + r;
#pragma unroll
        for (int j = 0; j < 5; j++) acc[j] += g_h2[n * 5 + j];
#pragma unroll
        for (int j = 0; j < 5; j++) acc[5 + j] += g_h1[n * 5 + j];
#pragma unroll
        for (int f = 0; f < 8; f++) acc[10 + f] += g_xn[n * 8 + f];
    }
#pragma unroll
    for (int off = 16; off > 0; off >>= 1)
#pragma unroll
        for (int f = 0; f < 18; f++) acc[f] += __shfl_xor_sync(0xffffffffu, acc[f], off);
    __shared__ float sm[8][18];
    int wp = tid >> 5, lane = tid & 31;
    if (lane == 0) {
#pragma unroll
        for (int f = 0; f < 18; f++) sm[wp][f] = acc[f];
    }
    __syncthreads();
    if (tid < 18) {
        float t = 0.f;
        for (int k = 0; k < 8; k++) t += sm[k][tid];
        g_pool[g * 18 + tid] = t * (1.f / (float)NPER);
    }
}

// ---------------- dueling head ----------------
__global__ void k_head(const int* __restrict__ cur, const int* __restrict__ mask,
                       const float* __restrict__ goal,
                       const float* __restrict__ Wv1, const float* __restrict__ bv1,
                       const float* __restrict__ Wv2, const float* __restrict__ bv2,
                       const float* __restrict__ Wa1, const float* __restrict__ ba1,
                       const float* __restrict__ Wa2, const float* __restrict__ ba2,
                       float* __restrict__ out) {
    int b = threadIdx.x;
    if (b >= NB) return;
    int n = b * NPER + cur[b];
    float feat[42];
#pragma unroll
    for (int j = 0; j < 5; j++) feat[j] = g_h2[n * 5 + j];
#pragma unroll
    for (int j = 0; j < 5; j++) feat[5 + j] = g_h1[n * 5 + j];
#pragma unroll
    for (int f = 0; f < 8; f++) feat[10 + f] = g_xn[n * 8 + f];
#pragma unroll
    for (int k = 0; k < 18; k++) feat[18 + k] = g_pool[b * 18 + k];
#pragma unroll
    for (int k = 0; k < 6; k++) feat[36 + k] = goal[b * 6 + k];

    float hv[10], ha[10];
#pragma unroll
    for (int j = 0; j < 10; j++) { hv[j] = bv1[j]; ha[j] = ba1[j]; }
    for (int i = 0; i < 42; i++) {
        float fi = feat[i];
#pragma unroll
        for (int j = 0; j < 10; j++) {
            hv[j] = fmaf(fi, Wv1[i * 10 + j], hv[j]);
            ha[j] = fmaf(fi, Wa1[i * 10 + j], ha[j]);
        }
    }
#pragma unroll
    for (int j = 0; j < 10; j++) {
        hv[j] = (hv[j] > 0.f) ? hv[j] : 0.f;
        ha[j] = (ha[j] > 0.f) ? ha[j] : 0.f;
    }
    float val = bv2[0];
#pragma unroll
    for (int j = 0; j < 10; j++) val = fmaf(hv[j], Wv2[j], val);
    float adv[4];
#pragma unroll
    for (int k = 0; k < 4; k++) {
        adv[k] = ba2[k];
#pragma unroll
        for (int j = 0; j < 10; j++) adv[k] = fmaf(ha[j], Wa2[j * 4 + k], adv[k]);
    }
    float am = (adv[0] + adv[1] + adv[2] + adv[3]) * 0.25f;
#pragma unroll
    for (int k = 0; k < 4; k++)
        out[b * 4 + k] = (mask[b * 4 + k] == 0) ? -1e8f : (val + adv[k] - am);
}

// ---------------- launch ----------------
extern "C" void kernel_launch(void* const* d_in, const int* in_sizes, int n_in,
                              void* d_out, int out_size) {
    const float* x    = (const float*)d_in[0];
    const int*   ei   = (const int*)d_in[1];
    const float* ea   = (const float*)d_in[2];
    const int*   cur  = (const int*)d_in[4];
    const int*   mask = (const int*)d_in[5];
    const float* goal = (const float*)d_in[6];
    const float* gnw  = (const float*)d_in[7];
    const float* gnb  = (const float*)d_in[8];
    const float* gnms = (const float*)d_in[9];
    const float* Wl1 = (const float*)d_in[10], *bl1 = (const float*)d_in[11];
    const float* Wr1 = (const float*)d_in[12], *br1 = (const float*)d_in[13];
    const float* We1 = (const float*)d_in[14], *att1 = (const float*)d_in[15], *bo1 = (const float*)d_in[16];
    const float* Wl2 = (const float*)d_in[17], *bl2 = (const float*)d_in[18];
    const float* Wr2 = (const float*)d_in[19], *br2 = (const float*)d_in[20];
    const float* We2 = (const float*)d_in[21], *att2 = (const float*)d_in[22], *bo2 = (const float*)d_in[23];
    const float* Wv1 = (const float*)d_in[24], *bv1 = (const float*)d_in[25];
    const float* Wv2 = (const float*)d_in[26], *bv2 = (const float*)d_in[27];
    const float* Wa1 = (const float*)d_in[28], *ba1 = (const float*)d_in[29];
    const float* Wa2 = (const float*)d_in[30], *ba2 = (const float*)d_in[31];

    const int* srcp = ei;
    const int* dstp = ei + NE;

    k_zero<<<(NN + 255) / 256, 256>>>();
    k_gn<<<NB, 256>>>(x, gnw, gnb, gnms);
    k_count<<<2048, 256>>>(dstp);
    k_scanA<<<512, 1024>>>();
    k_scanB<<<1, 512>>>();
    k_scanC<<<512, 1024>>>();
    k_scatter<<<2048, 256>>>(srcp, dstp, ea);
    k_eamean<<<1, 32>>>();

    k_lr<false><<<(NN + 255) / 256, 256>>>(Wl1, bl1, Wr1, br1);
    k_gat<1><<<NN / 8, 256>>>(We1, att1, bo1);

    k_lr<true><<<(NN + 255) / 256, 256>>>(Wl2, bl2, Wr2, br2);
    k_gat<2><<<NN / 8, 256>>>(We2, att2, bo2);

    k_pool<<<NB, 256>>>();
    k_head<<<1, 64>>>(cur, mask, goal, Wv1, bv1, Wv2, bv2, Wa1, ba1, Wa2, ba2,
                      (float*)d_out);
}